// round 13
// baseline (speedup 1.0000x reference)
#include <cuda_runtime.h>
#include <cuda_fp16.h>
#include <math.h>

#define NFFT   384
#define TT     16              // transforms per block
#define ES     17              // padded smem stride (in float2 units)
#define HW     147456          // 384*384
#define NIMG   96              // 32 batch * 3 channels
#define NCH    3
#define W193   193             // stored half-spectrum columns
#define SPI    (W193*NFFT)     // 74112 complex per image
#define BLOCK  768
#define BUF    (NFFT*ES)       // 6528 float2 per complex plane
#define SMEM_F2     (2*BUF + NFFT + NFFT)   // A, B, tw, amp(768 floats = 384 f2)
#define SMEM_BYTES  (SMEM_F2*8)
#define ROWTILES 12            // 32 real rows (16 packed FFTs) per block
#define ROWG   (NIMG*ROWTILES) // 1152
#define PREPG  ((NCH*SPI + BLOCK - 1)/BLOCK)   // 290
#define COLG   (3*96 + 3)      // 288 two-col tiles + 3 single-col (w=192) = 291
#define TWO_PI 6.283185307179586476925286766559

// ---------------- device scratch ----------------
__device__ float2  g_spec [NIMG*SPI];   // 57 MB fp32 spectrum (fwd -> inv inside col_fused)
__device__ __half2 g_specH[NIMG*SPI];   // 28.5 MB fp16 spectrum (row legs)
__device__ float   g_runT[NCH*SPI];     // symmetrized+transposed running_amp
__device__ float   g_rsum[1];
__device__ float2  g_tw[NFFT];          // forward twiddles exp(-2*pi*i*k/384)

// ---------------- complex / half helpers ----------------
__device__ __forceinline__ float2 cadd(float2 a, float2 b){ return make_float2(a.x+b.x, a.y+b.y); }
__device__ __forceinline__ float2 csub(float2 a, float2 b){ return make_float2(a.x-b.x, a.y-b.y); }
__device__ __forceinline__ float2 cscale(float s, float2 a){ return make_float2(s*a.x, s*a.y); }
__device__ __forceinline__ float2 mi(float2 z){ return make_float2(z.y, -z.x); }   // -i*z
template<int SGN>
__device__ __forceinline__ float2 cmul_t(float2 a, float2 b)    // SGN<0: a*conj(b)
{
    if (SGN > 0) return make_float2(a.x*b.x - a.y*b.y, a.x*b.y + a.y*b.x);
    else         return make_float2(a.x*b.x + a.y*b.y, a.y*b.x - a.x*b.y);
}
__device__ __forceinline__ unsigned f2h(float2 v)
{
    __half2 h = __float22half2_rn(v);
    return *reinterpret_cast<unsigned*>(&h);
}
__device__ __forceinline__ float2 h2f(unsigned u)
{
    __half2 h = *reinterpret_cast<__half2*>(&u);
    return __half22float2(h);
}

// ---------------- butterflies (S=+1 fwd, S=-1 inv) ----------------
__device__ __forceinline__ void bfly8(float S, const float2 a[8], float2 b[8])
{
    const float c = 0.70710678118654752440f;
    float2 t0 = cadd(a[0], a[4]);
    float2 t1 = csub(a[0], a[4]);
    float2 t2 = cadd(a[2], a[6]);
    float2 t3 = csub(a[2], a[6]);
    float2 E0 = cadd(t0, t2);
    float2 E2 = csub(t0, t2);
    float2 mt3 = cscale(S, mi(t3));
    float2 E1 = cadd(t1, mt3);
    float2 E3 = csub(t1, mt3);
    float2 u0 = cadd(a[1], a[5]);
    float2 u1 = csub(a[1], a[5]);
    float2 u2 = cadd(a[3], a[7]);
    float2 u3 = csub(a[3], a[7]);
    float2 O0 = cadd(u0, u2);
    float2 O2 = csub(u0, u2);
    float2 mu3 = cscale(S, mi(u3));
    float2 O1 = cadd(u1, mu3);
    float2 O3 = csub(u1, mu3);
    float2 w1 = cscale(c,  cadd(O1, cscale(S, mi(O1))));
    float2 w2 = cscale(S,  mi(O2));
    float2 w3 = cscale(-c, csub(O3, cscale(S, mi(O3))));
    b[0] = cadd(E0, O0);  b[4] = csub(E0, O0);
    b[1] = cadd(E1, w1);  b[5] = csub(E1, w1);
    b[2] = cadd(E2, w2);  b[6] = csub(E2, w2);
    b[3] = cadd(E3, w3);  b[7] = csub(E3, w3);
}

__device__ __forceinline__ void bfly6(float S, const float2 a[6], float2 b[6])
{
    const float s3 = 0.86602540378443864676f;
    float2 t1 = cadd(a[2], a[4]);
    float2 E0 = cadd(a[0], t1);
    float2 t2 = csub(a[0], cscale(0.5f, t1));
    float2 t3 = cscale(s3, csub(a[2], a[4]));
    float2 mt3 = cscale(S, mi(t3));
    float2 E1 = cadd(t2, mt3);
    float2 E2 = csub(t2, mt3);
    float2 v1 = cadd(a[3], a[5]);
    float2 O0 = cadd(a[1], v1);
    float2 v2 = csub(a[1], cscale(0.5f, v1));
    float2 v3 = cscale(s3, csub(a[3], a[5]));
    float2 mv3 = cscale(S, mi(v3));
    float2 O1 = cadd(v2, mv3);
    float2 O2 = csub(v2, mv3);
    float2 w1 = cadd(cscale( 0.5f, O1), cscale(S*s3, mi(O1)));
    float2 w2 = cadd(cscale(-0.5f, O2), cscale(S*s3, mi(O2)));
    b[0] = cadd(E0, O0);  b[3] = csub(E0, O0);
    b[1] = cadd(E1, w1);  b[4] = csub(E1, w1);
    b[2] = cadd(E2, w2);  b[5] = csub(E2, w2);
}

// local twiddle build (sincosf) — for k_row_fwd which runs before g_tw is published
__device__ __forceinline__ void build_tw_local(float2* tw)
{
    const int k = threadIdx.x;
    if (k < NFFT) {
        float sv, cv;
        sincosf((float)k * (float)(TWO_PI/384.0), &sv, &cv);
        tw[k] = make_float2(cv, -sv);
    }
}
// copy twiddle table gmem -> smem (later kernels)
__device__ __forceinline__ void load_tw(float2* tw)
{
    const int k = threadIdx.x;
    if (k < NFFT) tw[k] = g_tw[k];
}

// ---------------- FFT stages 1-2 (radix-8, radix-8): A -> B -> A ----------------
template<int SGN>
__device__ __forceinline__ void fft384_stages12(float2* A, float2* B, const float2* __restrict__ tw)
{
    constexpr float S = (float)SGN;
    {   // stage 1: radix-8, s=1, A->B : 1 item/thread
        const int t = threadIdx.x & (TT-1);
        const int p = threadIdx.x >> 4;
        float2 a[8], b[8];
#pragma unroll
        for (int j = 0; j < 8; ++j) a[j] = A[(p + 48*j)*ES + t];
        bfly8(S, a, b);
#pragma unroll
        for (int j = 1; j < 8; ++j) b[j] = cmul_t<SGN>(b[j], tw[p*j]);
#pragma unroll
        for (int j = 0; j < 8; ++j) B[(8*p + j)*ES + t] = b[j];
    }
    __syncthreads();
    {   // stage 2: radix-8, s=8, B->A : 1 item/thread
        const int t = threadIdx.x & (TT-1);
        const int u = threadIdx.x >> 4;
        const int q = u & 7;
        const int p = u >> 3;
        const int base = q + 8*p;
        float2 a[8], b[8];
#pragma unroll
        for (int j = 0; j < 8; ++j) a[j] = B[(base + 48*j)*ES + t];
        bfly8(S, a, b);
#pragma unroll
        for (int j = 1; j < 8; ++j) b[j] = cmul_t<SGN>(b[j], tw[8*p*j]);
#pragma unroll
        for (int j = 0; j < 8; ++j) A[(q + 64*p + 8*j)*ES + t] = b[j];
    }
    __syncthreads();
}

// generic stage-3 (t-major) item, used only by k_row_fwd
template<int SGN>
__device__ __forceinline__ void stage3_item(int i, const float2* A, float2* B)
{
    constexpr float S = (float)SGN;
    const int t = i & (TT-1);
    const int q = i >> 4;
    float2 a[6], b[6];
#pragma unroll
    for (int j = 0; j < 6; ++j) a[j] = A[(q + 64*j)*ES + t];
    bfly6(S, a, b);
#pragma unroll
    for (int j = 0; j < 6; ++j) B[(q + 64*j)*ES + t] = b[j];
}

template<int SGN>
__device__ __forceinline__ void fft384_tile(float2* A, float2* B, const float2* __restrict__ tw)
{
    fft384_stages12<SGN>(A, B, tw);
    stage3_item<SGN>(threadIdx.x, A, B);
    if (threadIdx.x < TT*64 - BLOCK)
        stage3_item<SGN>(threadIdx.x + BLOCK, A, B);
    __syncthreads();
}

// q-major stage-3 item indices: i in [0,1024): q = i & 63, t = i >> 6.
// smem reads conflict-free; epilogue gmem stores coalesced (warp = fixed t, q consecutive).
#define STAGE3_QMAJOR(SGNF, EPILOGUE)                                         \
    for (int rep = 0; rep < 2; ++rep) {                                       \
        const int i = threadIdx.x + rep*BLOCK;                                \
        if (i < TT*64) {                                                      \
            const int q = i & 63;                                             \
            const int t = i >> 6;                                             \
            float2 a[6], b[6];                                                \
            _Pragma("unroll")                                                 \
            for (int j = 0; j < 6; ++j) a[j] = A[(q + 64*j)*ES + t];          \
            bfly6(SGNF, a, b);                                                \
            EPILOGUE                                                          \
        }                                                                     \
    }

// ---------------- prep body (runs as extra blocks of k_row_fwd) ----------------
__device__ __forceinline__ void prep_body(int pbid, const float* __restrict__ running)
{
    if (pbid == 0 && threadIdx.x < NFFT) {       // publish twiddle table for later kernels
        float sv, cv;
        sincosf((float)threadIdx.x * (float)(TWO_PI/384.0), &sv, &cv);
        g_tw[threadIdx.x] = make_float2(cv, -sv);
    }
    const int idx = pbid*BLOCK + threadIdx.x;
    float s = 0.f;
    if (idx < NCH*SPI) {
        const int ch = idx / SPI;
        const int rem = idx - ch*SPI;
        const int w = rem / NFFT;
        const int h = rem - w*NFFT;
        const int hm = (NFFT - h) % NFFT;
        const int wm = (NFFT - w) % NFFT;
        const float a = running[ch*HW + h*NFFT + w];
        const float b = running[ch*HW + hm*NFFT + wm];
        g_runT[idx] = 0.5f*(a + b);
        // full-plane sum: direct terms cover w in [0,192]; mirrors cover [193,383].
        s = a + ((w >= 1 && w <= 191) ? b : 0.f);
    }
#pragma unroll
    for (int o = 16; o > 0; o >>= 1) s += __shfl_down_sync(0xffffffffu, s, o);
    __shared__ float ws[BLOCK/32];
    if ((threadIdx.x & 31) == 0) ws[threadIdx.x >> 5] = s;
    __syncthreads();
    if (threadIdx.x < 32) {
        s = (threadIdx.x < BLOCK/32) ? ws[threadIdx.x] : 0.f;
#pragma unroll
        for (int o = 16; o > 0; o >>= 1) s += __shfl_down_sync(0xffffffffu, s, o);
        if (threadIdx.x == 0) atomicAdd(g_rsum, s);
    }
}

// ---------------- K1: packed row FFT + prep side blocks ----------------
__global__ void __launch_bounds__(BLOCK, 2) k_row_fwd(const float* __restrict__ x,
                                                      const float* __restrict__ running)
{
    if (blockIdx.x >= ROWG) { prep_body(blockIdx.x - ROWG, running); return; }

    extern __shared__ float2 sm[];
    float2* A = sm;  float2* B = sm + BUF;  float2* tw = sm + 2*BUF;
    build_tw_local(tw);

    const int img = blockIdx.x / ROWTILES;
    const int h0  = (blockIdx.x % ROWTILES) * 32;
    const float* xp = x + (size_t)img*HW + (size_t)h0*NFFT;

    const int r0 = threadIdx.x / NFFT;              // 0 or 1
    const int w  = threadIdx.x - r0*NFFT;           // 0..383
    const float* xb = xp + (size_t)(2*r0)*NFFT + w;
#pragma unroll
    for (int k = 0; k < 8; ++k) {                   // r = r0 + 2k
        A[w*ES + (r0 + 2*k)] =
            make_float2(xb[(size_t)(4*k)*NFFT], xb[(size_t)(4*k)*NFFT + NFFT]);
    }
    __syncthreads();
    fft384_tile<1>(A, B, tw);                       // packing needs mirrors: keep generic stage 3

    __half2* spH = g_specH + (size_t)img*SPI;
    for (int i = threadIdx.x; i < TT*W193; i += BLOCK) {
        const int t = i & (TT-1);
        const int ww = i >> 4;
        const int wm = ww ? NFFT - ww : 0;
        const float2 Z  = B[ww*ES + t];
        const float2 Zm = B[wm*ES + t];
        uint2 o2;
        o2.x = f2h(make_float2(0.5f*(Z.x + Zm.x), 0.5f*(Z.y - Zm.y)));   // F_even
        o2.y = f2h(make_float2(0.5f*(Z.y + Zm.y), 0.5f*(Zm.x - Z.x)));   // F_odd
        *reinterpret_cast<uint2*>(spH + (size_t)ww*NFFT + h0 + 2*t) = o2;
    }
}

// ---------------- K2: FUSED column FFT fwd + batch-mean amp + column IFFT ----------------
// One block owns all 32 images of one channel for a 2-column strip (or the single w=192 col).
// Amplitude mean lives in shared memory: no gmem atomics, no global sync, one wave.
__global__ void __launch_bounds__(BLOCK, 2) k_col_fused()
{
    extern __shared__ float2 sm[];
    float2* A = sm;  float2* B = sm + BUF;  float2* tw = sm + 2*BUF;
    float*  amp = reinterpret_cast<float*>(sm + 2*BUF + NFFT);   // 768 floats
    load_tw(tw);
    amp[threadIdx.x] = 0.f;                          // 768 entries exactly

    int ch, w0, ncols;
    if (blockIdx.x < 288) { ch = blockIdx.x / 96; w0 = (blockIdx.x % 96) * 2; ncols = 2; }
    else                  { ch = blockIdx.x - 288; w0 = 192;                  ncols = 1; }
    const int R = (ncols == 2) ? 4 : 2;              // rounds of 16 transforms

    const float rs = g_rsum[0];
    const float inv = 1.0f/147456.0f;                // full ifft2 normalization, folded here
    const int t0 = threadIdx.x / NFFT;               // 0 or 1
    const int h  = threadIdx.x - t0*NFFT;            // 0..383

    // transform t in round r -> (batch index, column)
#define MAP_T(T, R_, IB, W)                                                   \
    int IB, W;                                                                \
    if (ncols == 2) { IB = 8*(R_) + ((T) >> 1); W = w0 + ((T) & 1); }         \
    else            { IB = 16*(R_) + (T);       W = 192; }

    // ---------- forward phase: FFT all 32 images, accumulate amp in smem ----------
    for (int r = 0; r < R; ++r) {
#pragma unroll
        for (int k = 0; k < 8; ++k) {
            const int t = t0 + 2*k;
            MAP_T(t, r, ib, w)
            const int img = ib*NCH + ch;
            A[h*ES + t] = __half22float2(g_specH[(size_t)img*SPI + (size_t)w*NFFT + h]);
        }
        __syncthreads();
        fft384_stages12<1>(A, B, tw);
        STAGE3_QMAJOR(1.f,
            MAP_T(t, r, ib, w)
            const int img = ib*NCH + ch;
            float2* sp = g_spec + (size_t)img*SPI + (size_t)w*NFFT;
            float* ab = amp + ((ncols == 2) ? (t & 1)*NFFT : 0);
#pragma unroll
            for (int j = 0; j < 6; ++j) {
                const int hh = q + 64*j;
                sp[hh] = b[j];
                const float m2 = b[j].x*b[j].x + b[j].y*b[j].y;
                atomicAdd(&ab[hh], (m2 > 0.f) ? m2*rsqrtf(m2) : 0.f);
            }
        )
        __syncthreads();                             // amp + A/B reuse safe
    }

    // ---------- inverse phase: scale by mean amp (smem), IFFT, fp16 store ----------
    for (int r = 0; r < R; ++r) {
#pragma unroll
        for (int k = 0; k < 8; ++k) {
            const int t = t0 + 2*k;
            MAP_T(t, r, ib, w)
            const int img = ib*NCH + ch;
            const size_t off = (size_t)img*SPI + (size_t)w*NFFT + h;
            const float2 v = g_spec[off];            // written by this block (synced)
            const float mean = amp[((ncols == 2) ? (t & 1)*NFFT : 0) + h] * (1.0f/32.0f);
            float na = mean;
            if (rs != 0.0f)
                na = 0.9f*g_runT[(size_t)ch*SPI + (size_t)w*NFFT + h] + 0.1f*mean;
            na *= inv;
            const float m2 = v.x*v.x + v.y*v.y;
            A[h*ES + t] = (m2 > 0.0f) ? cscale(na*rsqrtf(m2), v) : make_float2(na, 0.f);
        }
        __syncthreads();
        fft384_stages12<-1>(A, B, tw);
        STAGE3_QMAJOR(-1.f,
            MAP_T(t, r, ib, w)
            const int img = ib*NCH + ch;
            __half2* spH = g_specH + (size_t)img*SPI + (size_t)w*NFFT;
#pragma unroll
            for (int j = 0; j < 6; ++j)
                spH[q + 64*j] = __float22half2_rn(b[j]);
        )
        __syncthreads();
    }
#undef MAP_T
}

// ---------------- K3: packed row IFFT (C2R, fused register->gmem epilogue) ----------------
__global__ void __launch_bounds__(BLOCK, 2) k_row_inv(float* __restrict__ out)
{
    extern __shared__ float2 sm[];
    float2* A = sm;  float2* B = sm + BUF;  float2* tw = sm + 2*BUF;
    load_tw(tw);

    const int img = blockIdx.x / ROWTILES;
    const int h0  = (blockIdx.x % ROWTILES) * 32;
    const __half2* spH = g_specH + (size_t)img*SPI;
    for (int i = threadIdx.x; i < TT*W193; i += BLOCK) {
        const int t = i & (TT-1);
        const int w = i >> 4;
        uint2 zz = *reinterpret_cast<const uint2*>(spH + (size_t)w*NFFT + h0 + 2*t);
        const float2 ze = h2f(zz.x), zo = h2f(zz.y);
        // W[w] = Z_e + i*Z_o ;  W[384-w] = conj(Z_e) + i*conj(Z_o)
        A[w*ES + t] = make_float2(ze.x - zo.y, ze.y + zo.x);
        if (w >= 1 && w <= 191)
            A[(NFFT - w)*ES + t] = make_float2(ze.x + zo.y, zo.x - ze.y);
    }
    __syncthreads();
    fft384_stages12<-1>(A, B, tw);

    float* op = out + (size_t)img*HW + (size_t)h0*NFFT;   // norm already folded in col_fused
    STAGE3_QMAJOR(-1.f,
        float* o0 = op + (size_t)(2*t)*NFFT;
        float* o1 = o0 + NFFT;
#pragma unroll
        for (int j = 0; j < 6; ++j) {
            const int w = q + 64*j;
            o0[w] = b[j].x;       // even output row 2t
            o1[w] = b[j].y;       // odd output row 2t+1
        }
    )
}

// ---------------- launch ----------------
extern "C" void kernel_launch(void* const* d_in, const int* in_sizes, int n_in,
                              void* d_out, int out_size)
{
    const float* x       = (const float*)d_in[0];
    const float* running = (const float*)d_in[1];
    float* out = (float*)d_out;

    void* p_rs = nullptr; cudaGetSymbolAddress(&p_rs, g_rsum);

    cudaFuncSetAttribute(k_row_fwd,   cudaFuncAttributeMaxDynamicSharedMemorySize, SMEM_BYTES);
    cudaFuncSetAttribute(k_col_fused, cudaFuncAttributeMaxDynamicSharedMemorySize, SMEM_BYTES);
    cudaFuncSetAttribute(k_row_inv,   cudaFuncAttributeMaxDynamicSharedMemorySize, SMEM_BYTES);

    cudaMemsetAsync(p_rs, 0, sizeof(float));

    k_row_fwd<<<ROWG + PREPG, BLOCK, SMEM_BYTES>>>(x, running);
    k_col_fused<<<COLG, BLOCK, SMEM_BYTES>>>();
    k_row_inv<<<NIMG*ROWTILES, BLOCK, SMEM_BYTES>>>(out);
}

// round 14
// speedup vs baseline: 1.7216x; 1.7216x over previous
#include <cuda_runtime.h>
#include <cuda_fp16.h>
#include <math.h>

#define NFFT   384
#define TT     16              // transforms per block
#define ES     17              // padded smem stride (in float2 units)
#define HW     147456          // 384*384
#define NIMG   96              // 32 batch * 3 channels
#define NCH    3
#define IPC    32              // images per channel
#define W193   193             // stored half-spectrum columns
#define SPI    (W193*NFFT)     // 74112 complex per image
#define BLOCK  768
#define BUF    (NFFT*ES)       // 6528 float2 per complex plane
#define SMEM_F2     (2*BUF + NFFT)
#define SMEM_BYTES  (SMEM_F2*8)
#define ROWTILES 12            // 32 real rows (16 packed FFTs) per block
#define COLFULL  12            // full col tiles per image (w=0..191)
#define ROWCH  (IPC*ROWTILES)  // 384 row blocks per channel
#define COLCH  (IPC*COLFULL + IPC/TT)   // 384 + 2 = 386 col blocks per channel
#define PREPG  290             // total prep blocks (NCH*SPI/768 rounded up)
#define TWO_PI 6.283185307179586476925286766559

// ---------------- device scratch ----------------
__device__ float2  g_spec [NIMG*SPI];   // 57 MB fp32 spectrum (col_fwd -> col_inv leg)
__device__ __half2 g_specH[NIMG*SPI];   // 28.5 MB fp16 spectrum (row legs)
__device__ float   g_ampsum[NCH*SPI];   // batch-summed amplitude, transposed
__device__ float   g_runT[NCH*SPI];     // symmetrized+transposed running_amp
__device__ float   g_rsum[1];

// ---------------- complex / half helpers ----------------
__device__ __forceinline__ float2 cadd(float2 a, float2 b){ return make_float2(a.x+b.x, a.y+b.y); }
__device__ __forceinline__ float2 csub(float2 a, float2 b){ return make_float2(a.x-b.x, a.y-b.y); }
__device__ __forceinline__ float2 cscale(float s, float2 a){ return make_float2(s*a.x, s*a.y); }
__device__ __forceinline__ float2 mi(float2 z){ return make_float2(z.y, -z.x); }   // -i*z
template<int SGN>
__device__ __forceinline__ float2 cmul_t(float2 a, float2 b)    // SGN<0: a*conj(b)
{
    if (SGN > 0) return make_float2(a.x*b.x - a.y*b.y, a.x*b.y + a.y*b.x);
    else         return make_float2(a.x*b.x + a.y*b.y, a.y*b.x - a.x*b.y);
}
__device__ __forceinline__ unsigned f2h(float2 v)
{
    __half2 h = __float22half2_rn(v);
    return *reinterpret_cast<unsigned*>(&h);
}
__device__ __forceinline__ float2 h2f(unsigned u)
{
    __half2 h = *reinterpret_cast<__half2*>(&u);
    return __half22float2(h);
}

// ---------------- butterflies (S=+1 fwd, S=-1 inv) ----------------
__device__ __forceinline__ void bfly8(float S, const float2 a[8], float2 b[8])
{
    const float c = 0.70710678118654752440f;
    float2 t0 = cadd(a[0], a[4]);
    float2 t1 = csub(a[0], a[4]);
    float2 t2 = cadd(a[2], a[6]);
    float2 t3 = csub(a[2], a[6]);
    float2 E0 = cadd(t0, t2);
    float2 E2 = csub(t0, t2);
    float2 mt3 = cscale(S, mi(t3));
    float2 E1 = cadd(t1, mt3);
    float2 E3 = csub(t1, mt3);
    float2 u0 = cadd(a[1], a[5]);
    float2 u1 = csub(a[1], a[5]);
    float2 u2 = cadd(a[3], a[7]);
    float2 u3 = csub(a[3], a[7]);
    float2 O0 = cadd(u0, u2);
    float2 O2 = csub(u0, u2);
    float2 mu3 = cscale(S, mi(u3));
    float2 O1 = cadd(u1, mu3);
    float2 O3 = csub(u1, mu3);
    float2 w1 = cscale(c,  cadd(O1, cscale(S, mi(O1))));
    float2 w2 = cscale(S,  mi(O2));
    float2 w3 = cscale(-c, csub(O3, cscale(S, mi(O3))));
    b[0] = cadd(E0, O0);  b[4] = csub(E0, O0);
    b[1] = cadd(E1, w1);  b[5] = csub(E1, w1);
    b[2] = cadd(E2, w2);  b[6] = csub(E2, w2);
    b[3] = cadd(E3, w3);  b[7] = csub(E3, w3);
}

__device__ __forceinline__ void bfly6(float S, const float2 a[6], float2 b[6])
{
    const float s3 = 0.86602540378443864676f;
    float2 t1 = cadd(a[2], a[4]);
    float2 E0 = cadd(a[0], t1);
    float2 t2 = csub(a[0], cscale(0.5f, t1));
    float2 t3 = cscale(s3, csub(a[2], a[4]));
    float2 mt3 = cscale(S, mi(t3));
    float2 E1 = cadd(t2, mt3);
    float2 E2 = csub(t2, mt3);
    float2 v1 = cadd(a[3], a[5]);
    float2 O0 = cadd(a[1], v1);
    float2 v2 = csub(a[1], cscale(0.5f, v1));
    float2 v3 = cscale(s3, csub(a[3], a[5]));
    float2 mv3 = cscale(S, mi(v3));
    float2 O1 = cadd(v2, mv3);
    float2 O2 = csub(v2, mv3);
    float2 w1 = cadd(cscale( 0.5f, O1), cscale(S*s3, mi(O1)));
    float2 w2 = cadd(cscale(-0.5f, O2), cscale(S*s3, mi(O2)));
    b[0] = cadd(E0, O0);  b[3] = csub(E0, O0);
    b[1] = cadd(E1, w1);  b[4] = csub(E1, w1);
    b[2] = cadd(E2, w2);  b[5] = csub(E2, w2);
}

// every kernel builds forward twiddles locally (measured neutral vs table load)
__device__ __forceinline__ void build_tw_local(float2* tw)
{
    const int k = threadIdx.x;
    if (k < NFFT) {
        float sv, cv;
        sincosf((float)k * (float)(TWO_PI/384.0), &sv, &cv);
        tw[k] = make_float2(cv, -sv);
    }
}

// ---------------- FFT stages 1-2 (radix-8, radix-8): A -> B -> A ----------------
template<int SGN>
__device__ __forceinline__ void fft384_stages12(float2* A, float2* B, const float2* __restrict__ tw)
{
    constexpr float S = (float)SGN;
    {   // stage 1: radix-8, s=1, A->B : 1 item/thread
        const int t = threadIdx.x & (TT-1);
        const int p = threadIdx.x >> 4;
        float2 a[8], b[8];
#pragma unroll
        for (int j = 0; j < 8; ++j) a[j] = A[(p + 48*j)*ES + t];
        bfly8(S, a, b);
#pragma unroll
        for (int j = 1; j < 8; ++j) b[j] = cmul_t<SGN>(b[j], tw[p*j]);
#pragma unroll
        for (int j = 0; j < 8; ++j) B[(8*p + j)*ES + t] = b[j];
    }
    __syncthreads();
    {   // stage 2: radix-8, s=8, B->A : 1 item/thread
        const int t = threadIdx.x & (TT-1);
        const int u = threadIdx.x >> 4;
        const int q = u & 7;
        const int p = u >> 3;
        const int base = q + 8*p;
        float2 a[8], b[8];
#pragma unroll
        for (int j = 0; j < 8; ++j) a[j] = B[(base + 48*j)*ES + t];
        bfly8(S, a, b);
#pragma unroll
        for (int j = 1; j < 8; ++j) b[j] = cmul_t<SGN>(b[j], tw[8*p*j]);
#pragma unroll
        for (int j = 0; j < 8; ++j) A[(q + 64*p + 8*j)*ES + t] = b[j];
    }
    __syncthreads();
}

// generic stage-3 (t-major) item, used only by k_row_fwd
template<int SGN>
__device__ __forceinline__ void stage3_item(int i, const float2* A, float2* B)
{
    constexpr float S = (float)SGN;
    const int t = i & (TT-1);
    const int q = i >> 4;
    float2 a[6], b[6];
#pragma unroll
    for (int j = 0; j < 6; ++j) a[j] = A[(q + 64*j)*ES + t];
    bfly6(S, a, b);
#pragma unroll
    for (int j = 0; j < 6; ++j) B[(q + 64*j)*ES + t] = b[j];
}

template<int SGN>
__device__ __forceinline__ void fft384_tile(float2* A, float2* B, const float2* __restrict__ tw)
{
    fft384_stages12<SGN>(A, B, tw);
    stage3_item<SGN>(threadIdx.x, A, B);
    if (threadIdx.x < TT*64 - BLOCK)
        stage3_item<SGN>(threadIdx.x + BLOCK, A, B);
    __syncthreads();
}

// q-major stage-3: q = i & 63, t = i >> 6; smem reads conflict-free, epilogue coalesced
#define STAGE3_QMAJOR(SGNF, EPILOGUE)                                         \
    for (int rep = 0; rep < 2; ++rep) {                                       \
        const int i = threadIdx.x + rep*BLOCK;                                \
        if (i < TT*64) {                                                      \
            const int q = i & 63;                                             \
            const int t = i >> 6;                                             \
            float2 a[6], b[6];                                                \
            _Pragma("unroll")                                                 \
            for (int j = 0; j < 6; ++j) a[j] = A[(q + 64*j)*ES + t];          \
            bfly6(SGNF, a, b);                                                \
            EPILOGUE                                                          \
        }                                                                     \
    }

// ---------------- prep body (split across the 3 per-channel row_fwd kernels) ----------------
__device__ __forceinline__ void prep_body(int pbid, const float* __restrict__ running)
{
    const int idx = pbid*BLOCK + threadIdx.x;
    float s = 0.f;
    if (idx < NCH*SPI) {
        const int ch = idx / SPI;
        const int rem = idx - ch*SPI;
        const int w = rem / NFFT;
        const int h = rem - w*NFFT;
        const int hm = (NFFT - h) % NFFT;
        const int wm = (NFFT - w) % NFFT;
        const float a = running[ch*HW + h*NFFT + w];
        const float b = running[ch*HW + hm*NFFT + wm];
        g_runT[idx] = 0.5f*(a + b);
        // full-plane sum: direct terms cover w in [0,192]; mirrors cover [193,383].
        s = a + ((w >= 1 && w <= 191) ? b : 0.f);
    }
#pragma unroll
    for (int o = 16; o > 0; o >>= 1) s += __shfl_down_sync(0xffffffffu, s, o);
    __shared__ float ws[BLOCK/32];
    if ((threadIdx.x & 31) == 0) ws[threadIdx.x >> 5] = s;
    __syncthreads();
    if (threadIdx.x < 32) {
        s = (threadIdx.x < BLOCK/32) ? ws[threadIdx.x] : 0.f;
#pragma unroll
        for (int o = 16; o > 0; o >>= 1) s += __shfl_down_sync(0xffffffffu, s, o);
        if (threadIdx.x == 0) atomicAdd(g_rsum, s);
    }
}

// ---------------- K1: per-channel packed row FFT + prep side blocks ----------------
__global__ void __launch_bounds__(BLOCK, 2) k_row_fwd(const float* __restrict__ x,
                                                      const float* __restrict__ running,
                                                      int ch, int prep_base)
{
    if (blockIdx.x >= ROWCH) { prep_body(prep_base + (int)blockIdx.x - ROWCH, running); return; }

    extern __shared__ float2 sm[];
    float2* A = sm;  float2* B = sm + BUF;  float2* tw = sm + 2*BUF;
    build_tw_local(tw);

    const int img = (blockIdx.x / ROWTILES)*NCH + ch;
    const int h0  = (blockIdx.x % ROWTILES) * 32;
    const float* xp = x + (size_t)img*HW + (size_t)h0*NFFT;

    const int r0 = threadIdx.x / NFFT;              // 0 or 1
    const int w  = threadIdx.x - r0*NFFT;           // 0..383
    const float* xb = xp + (size_t)(2*r0)*NFFT + w;
#pragma unroll
    for (int k = 0; k < 8; ++k) {                   // r = r0 + 2k
        A[w*ES + (r0 + 2*k)] =
            make_float2(xb[(size_t)(4*k)*NFFT], xb[(size_t)(4*k)*NFFT + NFFT]);
    }
    __syncthreads();
    fft384_tile<1>(A, B, tw);                       // packing needs mirrors: keep generic stage 3

    __half2* spH = g_specH + (size_t)img*SPI;
    for (int i = threadIdx.x; i < TT*W193; i += BLOCK) {
        const int t = i & (TT-1);
        const int ww = i >> 4;
        const int wm = ww ? NFFT - ww : 0;
        const float2 Z  = B[ww*ES + t];
        const float2 Zm = B[wm*ES + t];
        uint2 o2;
        o2.x = f2h(make_float2(0.5f*(Z.x + Zm.x), 0.5f*(Z.y - Zm.y)));   // F_even
        o2.y = f2h(make_float2(0.5f*(Z.y + Zm.y), 0.5f*(Zm.x - Z.x)));   // F_odd
        *reinterpret_cast<uint2*>(spH + (size_t)ww*NFFT + h0 + 2*t) = o2;
    }
}

// ---------------- K2: per-channel column FFT fwd + amplitude accumulate ----------------
__global__ void __launch_bounds__(BLOCK, 2) k_col_fwd(int ch)
{
    extern __shared__ float2 sm[];
    float2* A = sm;  float2* B = sm + BUF;  float2* tw = sm + 2*BUF;
    build_tw_local(tw);

    const int t0 = threadIdx.x / NFFT;              // 0 or 1
    const int h  = threadIdx.x - t0*NFFT;           // 0..383

    if (blockIdx.x < IPC*COLFULL) {
        const int img = (blockIdx.x / COLFULL)*NCH + ch;
        const int w0  = (blockIdx.x % COLFULL) * TT;
        const __half2* spHi = g_specH + (size_t)img*SPI + (size_t)w0*NFFT;
        float2* sp = g_spec + (size_t)img*SPI + (size_t)w0*NFFT;
#pragma unroll
        for (int k = 0; k < 8; ++k) {
            const int t = t0 + 2*k;
            A[h*ES + t] = __half22float2(spHi[(size_t)t*NFFT + h]);
        }
        __syncthreads();
        fft384_stages12<1>(A, B, tw);

        float* ab = g_ampsum + (size_t)ch*SPI + (size_t)w0*NFFT;
        STAGE3_QMAJOR(1.f,
#pragma unroll
            for (int j = 0; j < 6; ++j) {
                const size_t o = (size_t)t*NFFT + (q + 64*j);
                sp[o] = b[j];
                const float m2 = b[j].x*b[j].x + b[j].y*b[j].y;
                const float amp = (m2 > 0.f) ? m2*rsqrtf(m2) : 0.f;
                atomicAdd(&ab[o], amp);
            }
        )
    } else {
        const int g = blockIdx.x - IPC*COLFULL;     // 0..1 (image group, w=192)
#pragma unroll
        for (int k = 0; k < 8; ++k) {
            const int t = t0 + 2*k;
            const int img = (g*TT + t)*NCH + ch;
            A[h*ES + t] = __half22float2(g_specH[(size_t)img*SPI + (size_t)192*NFFT + h]);
        }
        __syncthreads();
        fft384_stages12<1>(A, B, tw);

        STAGE3_QMAJOR(1.f,
            const int img = (g*TT + t)*NCH + ch;
            float2* sp = g_spec + (size_t)img*SPI + (size_t)192*NFFT;
            float* ab = g_ampsum + (size_t)ch*SPI + (size_t)192*NFFT;
#pragma unroll
            for (int j = 0; j < 6; ++j) {
                const int hh = q + 64*j;
                sp[hh] = b[j];
                const float m2 = b[j].x*b[j].x + b[j].y*b[j].y;
                const float amp = (m2 > 0.f) ? m2*rsqrtf(m2) : 0.f;
                atomicAdd(&ab[hh], amp);
            }
        )
    }
}

// ---------------- K3: per-channel amplitude swap + column IFFT ----------------
__global__ void __launch_bounds__(BLOCK, 2) k_col_inv(int ch)
{
    extern __shared__ float2 sm[];
    float2* A = sm;  float2* B = sm + BUF;  float2* tw = sm + 2*BUF;
    build_tw_local(tw);

    const float rs = g_rsum[0];
    const float inv = 1.0f/147456.0f;               // full ifft2 normalization, folded here
    const int t0 = threadIdx.x / NFFT;
    const int h  = threadIdx.x - t0*NFFT;

#define COLINV_LOAD(SPOFF, ABOFF, T)                                          \
    {                                                                         \
        const float2 v = g_spec[SPOFF];                                       \
        const float mean = g_ampsum[ABOFF] * (1.0f/32.0f);                    \
        float na = mean;                                                      \
        if (rs != 0.0f) na = 0.9f*g_runT[ABOFF] + 0.1f*mean;                  \
        na *= inv;                                                            \
        const float m2 = v.x*v.x + v.y*v.y;                                   \
        float2 o;                                                             \
        if (m2 > 0.0f) { const float sc = na * rsqrtf(m2); o = make_float2(v.x*sc, v.y*sc); } \
        else           { o = make_float2(na, 0.0f); }                         \
        A[h*ES + (T)] = o;                                                    \
    }

    if (blockIdx.x < IPC*COLFULL) {
        const int img = (blockIdx.x / COLFULL)*NCH + ch;
        const int w0  = (blockIdx.x % COLFULL) * TT;
        const size_t spb = (size_t)img*SPI + (size_t)w0*NFFT;
        const size_t abb = (size_t)ch*SPI + (size_t)w0*NFFT;
#pragma unroll 4
        for (int k = 0; k < 8; ++k) {
            const int t = t0 + 2*k;
            const size_t o = (size_t)t*NFFT + h;
            COLINV_LOAD(spb + o, abb + o, t)
        }
        __syncthreads();
        fft384_stages12<-1>(A, B, tw);

        __half2* spH = g_specH + spb;
        STAGE3_QMAJOR(-1.f,
#pragma unroll
            for (int j = 0; j < 6; ++j)
                spH[(size_t)t*NFFT + (q + 64*j)] = __float22half2_rn(b[j]);
        )
    } else {
        const int g = blockIdx.x - IPC*COLFULL;     // 0..1
#pragma unroll 4
        for (int k = 0; k < 8; ++k) {
            const int t = t0 + 2*k;
            const int img = (g*TT + t)*NCH + ch;
            const size_t spo = (size_t)img*SPI + (size_t)192*NFFT + h;
            const size_t abo = (size_t)ch*SPI + (size_t)192*NFFT + h;
            COLINV_LOAD(spo, abo, t)
        }
        __syncthreads();
        fft384_stages12<-1>(A, B, tw);

        STAGE3_QMAJOR(-1.f,
            const int img = (g*TT + t)*NCH + ch;
            __half2* spH = g_specH + (size_t)img*SPI + (size_t)192*NFFT;
#pragma unroll
            for (int j = 0; j < 6; ++j)
                spH[q + 64*j] = __float22half2_rn(b[j]);
        )
    }
#undef COLINV_LOAD
}

// ---------------- K4: per-channel packed row IFFT (C2R) ----------------
__global__ void __launch_bounds__(BLOCK, 2) k_row_inv(float* __restrict__ out, int ch)
{
    extern __shared__ float2 sm[];
    float2* A = sm;  float2* B = sm + BUF;  float2* tw = sm + 2*BUF;
    build_tw_local(tw);

    const int img = (blockIdx.x / ROWTILES)*NCH + ch;
    const int h0  = (blockIdx.x % ROWTILES) * 32;
    const __half2* spH = g_specH + (size_t)img*SPI;
    for (int i = threadIdx.x; i < TT*W193; i += BLOCK) {
        const int t = i & (TT-1);
        const int w = i >> 4;
        uint2 zz = *reinterpret_cast<const uint2*>(spH + (size_t)w*NFFT + h0 + 2*t);
        const float2 ze = h2f(zz.x), zo = h2f(zz.y);
        // W[w] = Z_e + i*Z_o ;  W[384-w] = conj(Z_e) + i*conj(Z_o)
        A[w*ES + t] = make_float2(ze.x - zo.y, ze.y + zo.x);
        if (w >= 1 && w <= 191)
            A[(NFFT - w)*ES + t] = make_float2(ze.x + zo.y, zo.x - ze.y);
    }
    __syncthreads();
    fft384_stages12<-1>(A, B, tw);

    float* op = out + (size_t)img*HW + (size_t)h0*NFFT;   // norm already folded in col_inv
    STAGE3_QMAJOR(-1.f,
        float* o0 = op + (size_t)(2*t)*NFFT;
        float* o1 = o0 + NFFT;
#pragma unroll
        for (int j = 0; j < 6; ++j) {
            const int w = q + 64*j;
            o0[w] = b[j].x;       // even output row 2t
            o1[w] = b[j].y;       // odd output row 2t+1
        }
    )
}

// ---------------- launch: 3 channel chains on 3 streams (captured fork/join DAG) ----------------
extern "C" void kernel_launch(void* const* d_in, const int* in_sizes, int n_in,
                              void* d_out, int out_size)
{
    const float* x       = (const float*)d_in[0];
    const float* running = (const float*)d_in[1];
    float* out = (float*)d_out;

    static cudaStream_t st[NCH];
    static cudaEvent_t evFork, evRow[NCH], evJoin[NCH];
    static bool inited = false;
    if (!inited) {
        for (int c = 0; c < NCH; ++c)
            cudaStreamCreateWithFlags(&st[c], cudaStreamNonBlocking);
        cudaEventCreateWithFlags(&evFork, cudaEventDisableTiming);
        for (int c = 0; c < NCH; ++c) {
            cudaEventCreateWithFlags(&evRow[c],  cudaEventDisableTiming);
            cudaEventCreateWithFlags(&evJoin[c], cudaEventDisableTiming);
        }
        inited = true;
    }

    void* p_rs = nullptr;  cudaGetSymbolAddress(&p_rs,  g_rsum);
    void* p_amp = nullptr; cudaGetSymbolAddress(&p_amp, g_ampsum);

    cudaFuncSetAttribute(k_row_fwd, cudaFuncAttributeMaxDynamicSharedMemorySize, SMEM_BYTES);
    cudaFuncSetAttribute(k_col_fwd, cudaFuncAttributeMaxDynamicSharedMemorySize, SMEM_BYTES);
    cudaFuncSetAttribute(k_col_inv, cudaFuncAttributeMaxDynamicSharedMemorySize, SMEM_BYTES);
    cudaFuncSetAttribute(k_row_inv, cudaFuncAttributeMaxDynamicSharedMemorySize, SMEM_BYTES);

    // zero rsum + ampsum on the captured (legacy) stream, then fork
    cudaMemsetAsync(p_rs,  0, sizeof(float));
    cudaMemsetAsync(p_amp, 0, (size_t)NCH*SPI*sizeof(float));
    cudaEventRecord(evFork, 0);

    const int prep_cnt[NCH]  = {97, 97, 96};      // 290 total
    const int prep_base[NCH] = {0, 97, 194};

    for (int c = 0; c < NCH; ++c) {
        cudaStreamWaitEvent(st[c], evFork, 0);
        k_row_fwd<<<ROWCH + prep_cnt[c], BLOCK, SMEM_BYTES, st[c]>>>(x, running, c, prep_base[c]);
        cudaEventRecord(evRow[c], st[c]);
    }
    for (int c = 0; c < NCH; ++c) {
        k_col_fwd<<<COLCH, BLOCK, SMEM_BYTES, st[c]>>>(c);
        // col_inv needs ALL prep (rsum/runT): wait on the other channels' row kernels
        cudaStreamWaitEvent(st[c], evRow[(c + 1) % NCH], 0);
        cudaStreamWaitEvent(st[c], evRow[(c + 2) % NCH], 0);
        k_col_inv<<<COLCH, BLOCK, SMEM_BYTES, st[c]>>>(c);
        k_row_inv<<<ROWCH, BLOCK, SMEM_BYTES, st[c]>>>(out, c);
        cudaEventRecord(evJoin[c], st[c]);
    }
    for (int c = 0; c < NCH; ++c)
        cudaStreamWaitEvent(0, evJoin[c], 0);      // join back to the captured stream
}

// round 16
// speedup vs baseline: 1.8008x; 1.0460x over previous
#include <cuda_runtime.h>
#include <cuda_fp16.h>
#include <math.h>

#define NFFT   384
#define TT     16              // transforms per block
#define ES     17              // padded smem stride (in float2 units)
#define HW     147456          // 384*384
#define NIMG   96              // 32 batch * 3 channels
#define NCH    3
#define IPC    32              // images per channel
#define W193   193             // stored half-spectrum columns
#define SPI    (W193*NFFT)     // 74112 complex per image
#define BLOCK  768
#define BUF    (NFFT*ES)       // 6528 float2 per complex plane
#define SMEM_F2     (2*BUF + NFFT)
#define SMEM_BYTES  (SMEM_F2*8)
#define ROWTILES 12            // 32 real rows (16 packed FFTs) per block
#define COLFULL  12            // full col tiles per image (w=0..191)
#define ROWCH  (IPC*ROWTILES)  // 384 row blocks per channel
#define COLCH  (IPC*COLFULL + IPC/TT)   // 384 + 2 = 386 col blocks per channel
#define TWO_PI 6.283185307179586476925286766559

// ---------------- device scratch ----------------
__device__ float2  g_spec [NIMG*SPI];   // 57 MB fp32 spectrum (col_fwd -> col_inv leg)
__device__ __half2 g_specH[NIMG*SPI];   // 28.5 MB fp16 spectrum (row legs)
__device__ float   g_ampsum[NCH*SPI];   // batch-summed amplitude, transposed
__device__ float   g_runT[NCH*SPI];     // symmetrized+transposed running_amp
__device__ float   g_rsum[1];

// ---------------- complex / half helpers ----------------
__device__ __forceinline__ float2 cadd(float2 a, float2 b){ return make_float2(a.x+b.x, a.y+b.y); }
__device__ __forceinline__ float2 csub(float2 a, float2 b){ return make_float2(a.x-b.x, a.y-b.y); }
__device__ __forceinline__ float2 cscale(float s, float2 a){ return make_float2(s*a.x, s*a.y); }
__device__ __forceinline__ float2 mi(float2 z){ return make_float2(z.y, -z.x); }   // -i*z
template<int SGN>
__device__ __forceinline__ float2 cmul_t(float2 a, float2 b)    // SGN<0: a*conj(b)
{
    if (SGN > 0) return make_float2(a.x*b.x - a.y*b.y, a.x*b.y + a.y*b.x);
    else         return make_float2(a.x*b.x + a.y*b.y, a.y*b.x - a.x*b.y);
}
__device__ __forceinline__ unsigned f2h(float2 v)
{
    __half2 h = __float22half2_rn(v);
    return *reinterpret_cast<unsigned*>(&h);
}
__device__ __forceinline__ float2 h2f(unsigned u)
{
    __half2 h = *reinterpret_cast<__half2*>(&u);
    return __half22float2(h);
}

// ---------------- butterflies (S=+1 fwd, S=-1 inv) ----------------
__device__ __forceinline__ void bfly8(float S, const float2 a[8], float2 b[8])
{
    const float c = 0.70710678118654752440f;
    float2 t0 = cadd(a[0], a[4]);
    float2 t1 = csub(a[0], a[4]);
    float2 t2 = cadd(a[2], a[6]);
    float2 t3 = csub(a[2], a[6]);
    float2 E0 = cadd(t0, t2);
    float2 E2 = csub(t0, t2);
    float2 mt3 = cscale(S, mi(t3));
    float2 E1 = cadd(t1, mt3);
    float2 E3 = csub(t1, mt3);
    float2 u0 = cadd(a[1], a[5]);
    float2 u1 = csub(a[1], a[5]);
    float2 u2 = cadd(a[3], a[7]);
    float2 u3 = csub(a[3], a[7]);
    float2 O0 = cadd(u0, u2);
    float2 O2 = csub(u0, u2);
    float2 mu3 = cscale(S, mi(u3));
    float2 O1 = cadd(u1, mu3);
    float2 O3 = csub(u1, mu3);
    float2 w1 = cscale(c,  cadd(O1, cscale(S, mi(O1))));
    float2 w2 = cscale(S,  mi(O2));
    float2 w3 = cscale(-c, csub(O3, cscale(S, mi(O3))));
    b[0] = cadd(E0, O0);  b[4] = csub(E0, O0);
    b[1] = cadd(E1, w1);  b[5] = csub(E1, w1);
    b[2] = cadd(E2, w2);  b[6] = csub(E2, w2);
    b[3] = cadd(E3, w3);  b[7] = csub(E3, w3);
}

__device__ __forceinline__ void bfly6(float S, const float2 a[6], float2 b[6])
{
    const float s3 = 0.86602540378443864676f;
    float2 t1 = cadd(a[2], a[4]);
    float2 E0 = cadd(a[0], t1);
    float2 t2 = csub(a[0], cscale(0.5f, t1));
    float2 t3 = cscale(s3, csub(a[2], a[4]));
    float2 mt3 = cscale(S, mi(t3));
    float2 E1 = cadd(t2, mt3);
    float2 E2 = csub(t2, mt3);
    float2 v1 = cadd(a[3], a[5]);
    float2 O0 = cadd(a[1], v1);
    float2 v2 = csub(a[1], cscale(0.5f, v1));
    float2 v3 = cscale(s3, csub(a[3], a[5]));
    float2 mv3 = cscale(S, mi(v3));
    float2 O1 = cadd(v2, mv3);
    float2 O2 = csub(v2, mv3);
    float2 w1 = cadd(cscale( 0.5f, O1), cscale(S*s3, mi(O1)));
    float2 w2 = cadd(cscale(-0.5f, O2), cscale(S*s3, mi(O2)));
    b[0] = cadd(E0, O0);  b[3] = csub(E0, O0);
    b[1] = cadd(E1, w1);  b[4] = csub(E1, w1);
    b[2] = cadd(E2, w2);  b[5] = csub(E2, w2);
}

// every kernel builds forward twiddles locally (measured neutral vs table load)
__device__ __forceinline__ void build_tw_local(float2* tw)
{
    const int k = threadIdx.x;
    if (k < NFFT) {
        float sv, cv;
        sincosf((float)k * (float)(TWO_PI/384.0), &sv, &cv);
        tw[k] = make_float2(cv, -sv);
    }
}

// ---------------- FFT stage pieces ----------------
template<int SGN>
__device__ __forceinline__ void fft_stage1_smem(float2* A, float2* B, const float2* __restrict__ tw)
{
    constexpr float S = (float)SGN;
    const int t = threadIdx.x & (TT-1);
    const int p = threadIdx.x >> 4;
    float2 a[8], b[8];
#pragma unroll
    for (int j = 0; j < 8; ++j) a[j] = A[(p + 48*j)*ES + t];
    bfly8(S, a, b);
#pragma unroll
    for (int j = 1; j < 8; ++j) b[j] = cmul_t<SGN>(b[j], tw[p*j]);
#pragma unroll
    for (int j = 0; j < 8; ++j) B[(8*p + j)*ES + t] = b[j];
}

template<int SGN>
__device__ __forceinline__ void fft_stage2(float2* A, float2* B, const float2* __restrict__ tw)
{
    constexpr float S = (float)SGN;
    const int t = threadIdx.x & (TT-1);
    const int u = threadIdx.x >> 4;
    const int q = u & 7;
    const int p = u >> 3;
    const int base = q + 8*p;
    float2 a[8], b[8];
#pragma unroll
    for (int j = 0; j < 8; ++j) a[j] = B[(base + 48*j)*ES + t];
    bfly8(S, a, b);
#pragma unroll
    for (int j = 1; j < 8; ++j) b[j] = cmul_t<SGN>(b[j], tw[8*p*j]);
#pragma unroll
    for (int j = 0; j < 8; ++j) A[(q + 64*p + 8*j)*ES + t] = b[j];
}

template<int SGN>
__device__ __forceinline__ void fft384_stages12(float2* A, float2* B, const float2* __restrict__ tw)
{
    fft_stage1_smem<SGN>(A, B, tw);
    __syncthreads();
    fft_stage2<SGN>(A, B, tw);
    __syncthreads();
}

// generic stage-3 (t-major) item, used only by k_row_fwd
template<int SGN>
__device__ __forceinline__ void stage3_item(int i, const float2* A, float2* B)
{
    constexpr float S = (float)SGN;
    const int t = i & (TT-1);
    const int q = i >> 4;
    float2 a[6], b[6];
#pragma unroll
    for (int j = 0; j < 6; ++j) a[j] = A[(q + 64*j)*ES + t];
    bfly6(S, a, b);
#pragma unroll
    for (int j = 0; j < 6; ++j) B[(q + 64*j)*ES + t] = b[j];
}

template<int SGN>
__device__ __forceinline__ void fft384_tile(float2* A, float2* B, const float2* __restrict__ tw)
{
    fft384_stages12<SGN>(A, B, tw);
    stage3_item<SGN>(threadIdx.x, A, B);
    if (threadIdx.x < TT*64 - BLOCK)
        stage3_item<SGN>(threadIdx.x + BLOCK, A, B);
    __syncthreads();
}

// q-major stage-3: q = i & 63, t = i >> 6; smem reads conflict-free, epilogue coalesced
#define STAGE3_QMAJOR(SGNF, EPILOGUE)                                         \
    for (int rep = 0; rep < 2; ++rep) {                                       \
        const int i = threadIdx.x + rep*BLOCK;                                \
        if (i < TT*64) {                                                      \
            const int q = i & 63;                                             \
            const int t = i >> 6;                                             \
            float2 a[6], b[6];                                                \
            _Pragma("unroll")                                                 \
            for (int j = 0; j < 6; ++j) a[j] = A[(q + 64*j)*ES + t];          \
            bfly6(SGNF, a, b);                                                \
            EPILOGUE                                                          \
        }                                                                     \
    }

// ---------------- prep body (split across the 3 per-channel row_fwd kernels) ----------------
__device__ __forceinline__ void prep_body(int pbid, const float* __restrict__ running)
{
    const int idx = pbid*BLOCK + threadIdx.x;
    float s = 0.f;
    if (idx < NCH*SPI) {
        const int ch = idx / SPI;
        const int rem = idx - ch*SPI;
        const int w = rem / NFFT;
        const int h = rem - w*NFFT;
        const int hm = (NFFT - h) % NFFT;
        const int wm = (NFFT - w) % NFFT;
        const float a = running[ch*HW + h*NFFT + w];
        const float b = running[ch*HW + hm*NFFT + wm];
        g_runT[idx] = 0.5f*(a + b);
        // full-plane sum: direct terms cover w in [0,192]; mirrors cover [193,383].
        s = a + ((w >= 1 && w <= 191) ? b : 0.f);
    }
#pragma unroll
    for (int o = 16; o > 0; o >>= 1) s += __shfl_down_sync(0xffffffffu, s, o);
    __shared__ float ws[BLOCK/32];
    if ((threadIdx.x & 31) == 0) ws[threadIdx.x >> 5] = s;
    __syncthreads();
    if (threadIdx.x < 32) {
        s = (threadIdx.x < BLOCK/32) ? ws[threadIdx.x] : 0.f;
#pragma unroll
        for (int o = 16; o > 0; o >>= 1) s += __shfl_down_sync(0xffffffffu, s, o);
        if (threadIdx.x == 0) atomicAdd(g_rsum, s);
    }
}

// ---------------- K1: per-channel packed row FFT + prep side blocks ----------------
__global__ void __launch_bounds__(BLOCK, 2) k_row_fwd(const float* __restrict__ x,
                                                      const float* __restrict__ running,
                                                      int ch, int prep_base)
{
    if (blockIdx.x >= ROWCH) { prep_body(prep_base + (int)blockIdx.x - ROWCH, running); return; }

    extern __shared__ float2 sm[];
    float2* A = sm;  float2* B = sm + BUF;  float2* tw = sm + 2*BUF;
    build_tw_local(tw);

    const int img = (blockIdx.x / ROWTILES)*NCH + ch;
    const int h0  = (blockIdx.x % ROWTILES) * 32;
    const float* xp = x + (size_t)img*HW + (size_t)h0*NFFT;

    const int r0 = threadIdx.x / NFFT;              // 0 or 1
    const int w  = threadIdx.x - r0*NFFT;           // 0..383
    const float* xb = xp + (size_t)(2*r0)*NFFT + w;
#pragma unroll
    for (int k = 0; k < 8; ++k) {                   // r = r0 + 2k
        A[w*ES + (r0 + 2*k)] =
            make_float2(xb[(size_t)(4*k)*NFFT], xb[(size_t)(4*k)*NFFT + NFFT]);
    }
    __syncthreads();
    fft384_tile<1>(A, B, tw);                       // packing needs mirrors: keep generic stage 3

    __half2* spH = g_specH + (size_t)img*SPI;
    for (int i = threadIdx.x; i < TT*W193; i += BLOCK) {
        const int t = i & (TT-1);
        const int ww = i >> 4;
        const int wm = ww ? NFFT - ww : 0;
        const float2 Z  = B[ww*ES + t];
        const float2 Zm = B[wm*ES + t];
        uint2 o2;
        o2.x = f2h(make_float2(0.5f*(Z.x + Zm.x), 0.5f*(Z.y - Zm.y)));   // F_even
        o2.y = f2h(make_float2(0.5f*(Z.y + Zm.y), 0.5f*(Zm.x - Z.x)));   // F_odd
        *reinterpret_cast<uint2*>(spH + (size_t)ww*NFFT + h0 + 2*t) = o2;
    }
}

// ---------------- K2: per-channel column FFT fwd + amplitude accumulate ----------------
__global__ void __launch_bounds__(BLOCK, 2) k_col_fwd(int ch)
{
    extern __shared__ float2 sm[];
    float2* A = sm;  float2* B = sm + BUF;  float2* tw = sm + 2*BUF;
    build_tw_local(tw);

    const int t0 = threadIdx.x / NFFT;              // 0 or 1
    const int h  = threadIdx.x - t0*NFFT;           // 0..383

    if (blockIdx.x < IPC*COLFULL) {
        const int img = (blockIdx.x / COLFULL)*NCH + ch;
        const int w0  = (blockIdx.x % COLFULL) * TT;
        const __half2* spHi = g_specH + (size_t)img*SPI + (size_t)w0*NFFT;
        float2* sp = g_spec + (size_t)img*SPI + (size_t)w0*NFFT;
#pragma unroll
        for (int k = 0; k < 8; ++k) {
            const int t = t0 + 2*k;
            A[h*ES + t] = __half22float2(spHi[(size_t)t*NFFT + h]);
        }
        __syncthreads();
        fft384_stages12<1>(A, B, tw);

        float* ab = g_ampsum + (size_t)ch*SPI + (size_t)w0*NFFT;
        STAGE3_QMAJOR(1.f,
#pragma unroll
            for (int j = 0; j < 6; ++j) {
                const size_t o = (size_t)t*NFFT + (q + 64*j);
                sp[o] = b[j];
                const float m2 = b[j].x*b[j].x + b[j].y*b[j].y;
                const float amp = (m2 > 0.f) ? m2*rsqrtf(m2) : 0.f;
                atomicAdd(&ab[o], amp);
            }
        )
    } else {
        const int g = blockIdx.x - IPC*COLFULL;     // 0..1 (image group, w=192)
#pragma unroll
        for (int k = 0; k < 8; ++k) {
            const int t = t0 + 2*k;
            const int img = (g*TT + t)*NCH + ch;
            A[h*ES + t] = __half22float2(g_specH[(size_t)img*SPI + (size_t)192*NFFT + h]);
        }
        __syncthreads();
        fft384_stages12<1>(A, B, tw);

        STAGE3_QMAJOR(1.f,
            const int img = (g*TT + t)*NCH + ch;
            float2* sp = g_spec + (size_t)img*SPI + (size_t)192*NFFT;
            float* ab = g_ampsum + (size_t)ch*SPI + (size_t)192*NFFT;
#pragma unroll
            for (int j = 0; j < 6; ++j) {
                const int hh = q + 64*j;
                sp[hh] = b[j];
                const float m2 = b[j].x*b[j].x + b[j].y*b[j].y;
                const float amp = (m2 > 0.f) ? m2*rsqrtf(m2) : 0.f;
                atomicAdd(&ab[hh], amp);
            }
        )
    }
}

// ---------------- K3: per-channel amplitude swap + column IFFT ----------------
__global__ void __launch_bounds__(BLOCK, 2) k_col_inv(int ch)
{
    extern __shared__ float2 sm[];
    float2* A = sm;  float2* B = sm + BUF;  float2* tw = sm + 2*BUF;
    build_tw_local(tw);

    const float rs = g_rsum[0];
    const float inv = 1.0f/147456.0f;               // full ifft2 normalization, folded here
    const int t0 = threadIdx.x / NFFT;
    const int h  = threadIdx.x - t0*NFFT;

#define COLINV_LOAD(SPOFF, ABOFF, T)                                          \
    {                                                                         \
        const float2 v = g_spec[SPOFF];                                       \
        const float mean = g_ampsum[ABOFF] * (1.0f/32.0f);                    \
        float na = mean;                                                      \
        if (rs != 0.0f) na = 0.9f*g_runT[ABOFF] + 0.1f*mean;                  \
        na *= inv;                                                            \
        const float m2 = v.x*v.x + v.y*v.y;                                   \
        float2 o;                                                             \
        if (m2 > 0.0f) { const float sc = na * rsqrtf(m2); o = make_float2(v.x*sc, v.y*sc); } \
        else           { o = make_float2(na, 0.0f); }                         \
        A[h*ES + (T)] = o;                                                    \
    }

    if (blockIdx.x < IPC*COLFULL) {
        const int img = (blockIdx.x / COLFULL)*NCH + ch;
        const int w0  = (blockIdx.x % COLFULL) * TT;
        const size_t spb = (size_t)img*SPI + (size_t)w0*NFFT;
        const size_t abb = (size_t)ch*SPI + (size_t)w0*NFFT;
#pragma unroll 4
        for (int k = 0; k < 8; ++k) {
            const int t = t0 + 2*k;
            const size_t o = (size_t)t*NFFT + h;
            COLINV_LOAD(spb + o, abb + o, t)
        }
        __syncthreads();
        fft384_stages12<-1>(A, B, tw);

        __half2* spH = g_specH + spb;
        STAGE3_QMAJOR(-1.f,
#pragma unroll
            for (int j = 0; j < 6; ++j)
                spH[(size_t)t*NFFT + (q + 64*j)] = __float22half2_rn(b[j]);
        )
    } else {
        const int g = blockIdx.x - IPC*COLFULL;     // 0..1
#pragma unroll 4
        for (int k = 0; k < 8; ++k) {
            const int t = t0 + 2*k;
            const int img = (g*TT + t)*NCH + ch;
            const size_t spo = (size_t)img*SPI + (size_t)192*NFFT + h;
            const size_t abo = (size_t)ch*SPI + (size_t)192*NFFT + h;
            COLINV_LOAD(spo, abo, t)
        }
        __syncthreads();
        fft384_stages12<-1>(A, B, tw);

        STAGE3_QMAJOR(-1.f,
            const int img = (g*TT + t)*NCH + ch;
            __half2* spH = g_specH + (size_t)img*SPI + (size_t)192*NFFT;
#pragma unroll
            for (int j = 0; j < 6; ++j)
                spH[q + 64*j] = __float22half2_rn(b[j]);
        )
    }
#undef COLINV_LOAD
}

// ---------------- K4: per-channel packed row IFFT (C2R) ----------------
// Stage 1 reads the packed fp16 spectrum DIRECTLY from gmem, reconstructing the
// Hermitian mirror in registers — no smem staging pass, one fewer barrier.
__global__ void __launch_bounds__(BLOCK, 2) k_row_inv(float* __restrict__ out, int ch)
{
    extern __shared__ float2 sm[];
    float2* A = sm;  float2* B = sm + BUF;  float2* tw = sm + 2*BUF;
    build_tw_local(tw);

    const int img = (blockIdx.x / ROWTILES)*NCH + ch;
    const int h0  = (blockIdx.x % ROWTILES) * 32;
    const __half2* spH = g_specH + (size_t)img*SPI;

    __syncthreads();                                // tw visible before stage 1 uses it
    {   // ---- stage 1: gmem(fp16) -> B, mirror on the fly ----
        const int t = threadIdx.x & (TT-1);
        const int p = threadIdx.x >> 4;             // 0..47
        float2 a[8], b[8];
#pragma unroll
        for (int j = 0; j < 8; ++j) {
            const int e  = p + 48*j;                // 0..383
            const int em = (e <= 192) ? e : NFFT - e;
            uint2 zz = *reinterpret_cast<const uint2*>(spH + (size_t)em*NFFT + h0 + 2*t);
            const float2 ze = h2f(zz.x), zo = h2f(zz.y);
            // W[e] = Z_e + i*Z_o ; W[e>192] = conj(Z_e[384-e]) + i*conj(Z_o[384-e])
            a[j] = (e <= 192) ? make_float2(ze.x - zo.y, ze.y + zo.x)
                              : make_float2(ze.x + zo.y, zo.x - ze.y);
        }
        bfly8(-1.f, a, b);
#pragma unroll
        for (int j = 1; j < 8; ++j) b[j] = cmul_t<-1>(b[j], tw[p*j]);
#pragma unroll
        for (int j = 0; j < 8; ++j) B[(8*p + j)*ES + t] = b[j];
    }
    __syncthreads();
    fft_stage2<-1>(A, B, tw);
    __syncthreads();

    float* op = out + (size_t)img*HW + (size_t)h0*NFFT;   // norm already folded in col_inv
    STAGE3_QMAJOR(-1.f,
        float* o0 = op + (size_t)(2*t)*NFFT;
        float* o1 = o0 + NFFT;
#pragma unroll
        for (int j = 0; j < 6; ++j) {
            const int w = q + 64*j;
            o0[w] = b[j].x;       // even output row 2t
            o1[w] = b[j].y;       // odd output row 2t+1
        }
    )
}

// ---------------- launch: 3 channel chains on 3 streams (R14 structure, passes mem rules) ----
extern "C" void kernel_launch(void* const* d_in, const int* in_sizes, int n_in,
                              void* d_out, int out_size)
{
    const float* x       = (const float*)d_in[0];
    const float* running = (const float*)d_in[1];
    float* out = (float*)d_out;

    static cudaStream_t st[NCH];
    static cudaEvent_t evFork, evRow[NCH], evJoin[NCH];
    static bool inited = false;
    if (!inited) {
        for (int c = 0; c < NCH; ++c)
            cudaStreamCreateWithFlags(&st[c], cudaStreamNonBlocking);
        cudaEventCreateWithFlags(&evFork, cudaEventDisableTiming);
        for (int c = 0; c < NCH; ++c) {
            cudaEventCreateWithFlags(&evRow[c],  cudaEventDisableTiming);
            cudaEventCreateWithFlags(&evJoin[c], cudaEventDisableTiming);
        }
        inited = true;
    }

    void* p_rs = nullptr;  cudaGetSymbolAddress(&p_rs,  g_rsum);
    void* p_amp = nullptr; cudaGetSymbolAddress(&p_amp, g_ampsum);

    cudaFuncSetAttribute(k_row_fwd, cudaFuncAttributeMaxDynamicSharedMemorySize, SMEM_BYTES);
    cudaFuncSetAttribute(k_col_fwd, cudaFuncAttributeMaxDynamicSharedMemorySize, SMEM_BYTES);
    cudaFuncSetAttribute(k_col_inv, cudaFuncAttributeMaxDynamicSharedMemorySize, SMEM_BYTES);
    cudaFuncSetAttribute(k_row_inv, cudaFuncAttributeMaxDynamicSharedMemorySize, SMEM_BYTES);

    // zero rsum + ampsum on the captured (legacy) stream, then fork
    cudaMemsetAsync(p_rs,  0, sizeof(float));
    cudaMemsetAsync(p_amp, 0, (size_t)NCH*SPI*sizeof(float));
    cudaEventRecord(evFork, 0);

    const int prep_cnt[NCH]  = {97, 97, 96};      // 290 total
    const int prep_base[NCH] = {0, 97, 194};

    for (int c = 0; c < NCH; ++c) {
        cudaStreamWaitEvent(st[c], evFork, 0);
        k_row_fwd<<<ROWCH + prep_cnt[c], BLOCK, SMEM_BYTES, st[c]>>>(x, running, c, prep_base[c]);
        cudaEventRecord(evRow[c], st[c]);
    }
    for (int c = 0; c < NCH; ++c) {
        k_col_fwd<<<COLCH, BLOCK, SMEM_BYTES, st[c]>>>(c);
        // col_inv needs ALL prep (rsum/runT): wait on the other channels' row kernels
        cudaStreamWaitEvent(st[c], evRow[(c + 1) % NCH], 0);
        cudaStreamWaitEvent(st[c], evRow[(c + 2) % NCH], 0);
        k_col_inv<<<COLCH, BLOCK, SMEM_BYTES, st[c]>>>(c);
        k_row_inv<<<ROWCH, BLOCK, SMEM_BYTES, st[c]>>>(out, c);
        cudaEventRecord(evJoin[c], st[c]);
    }
    for (int c = 0; c < NCH; ++c)
        cudaStreamWaitEvent(0, evJoin[c], 0);      // join back to the captured stream
}

// round 17
// speedup vs baseline: 1.8013x; 1.0003x over previous
#include <cuda_runtime.h>
#include <cuda_fp16.h>
#include <math.h>

#define NFFT   384
#define TT     16              // transforms per block
#define ES     17              // padded smem stride (in float2 units)
#define HW     147456          // 384*384
#define NIMG   96              // 32 batch * 3 channels
#define NCH    3
#define IPC    32              // images per channel
#define W193   193             // stored half-spectrum columns
#define SPI    (W193*NFFT)     // 74112 complex per image
#define BLOCK  768
#define BUF    (NFFT*ES)       // 6528 float2 per complex plane
#define SMEM_F2     (2*BUF + NFFT)
#define SMEM_BYTES  (SMEM_F2*8)
#define ROWTILES 12            // 32 real rows (16 packed FFTs) per block
#define COLFULL  12            // full col tiles per image (w=0..191)
#define ROWCH  (IPC*ROWTILES)  // 384 row blocks per channel
#define COLCH  (IPC*COLFULL + IPC/TT)   // 384 + 2 = 386 col blocks per channel
#define PREPC  25              // prep blocks per channel: ceil(SPI / (768*4))
#define TWO_PI 6.283185307179586476925286766559

// ---------------- device scratch ----------------
__device__ float2  g_spec [NIMG*SPI];   // 57 MB fp32 spectrum (col_fwd -> col_inv leg)
__device__ __half2 g_specH[NIMG*SPI];   // 28.5 MB fp16 spectrum (row legs)
__device__ float   g_ampsum[NCH*SPI];   // batch-summed amplitude, transposed
__device__ float   g_runT[NCH*SPI];     // symmetrized+transposed running_amp
__device__ float   g_rsum[1];

// ---------------- complex / half helpers ----------------
__device__ __forceinline__ float2 cadd(float2 a, float2 b){ return make_float2(a.x+b.x, a.y+b.y); }
__device__ __forceinline__ float2 csub(float2 a, float2 b){ return make_float2(a.x-b.x, a.y-b.y); }
__device__ __forceinline__ float2 cscale(float s, float2 a){ return make_float2(s*a.x, s*a.y); }
__device__ __forceinline__ float2 mi(float2 z){ return make_float2(z.y, -z.x); }   // -i*z
template<int SGN>
__device__ __forceinline__ float2 cmul_t(float2 a, float2 b)    // SGN<0: a*conj(b)
{
    if (SGN > 0) return make_float2(a.x*b.x - a.y*b.y, a.x*b.y + a.y*b.x);
    else         return make_float2(a.x*b.x + a.y*b.y, a.y*b.x - a.x*b.y);
}
__device__ __forceinline__ unsigned f2h(float2 v)
{
    __half2 h = __float22half2_rn(v);
    return *reinterpret_cast<unsigned*>(&h);
}
__device__ __forceinline__ float2 h2f(unsigned u)
{
    __half2 h = *reinterpret_cast<__half2*>(&u);
    return __half22float2(h);
}

// ---------------- butterflies (S=+1 fwd, S=-1 inv) ----------------
__device__ __forceinline__ void bfly8(float S, const float2 a[8], float2 b[8])
{
    const float c = 0.70710678118654752440f;
    float2 t0 = cadd(a[0], a[4]);
    float2 t1 = csub(a[0], a[4]);
    float2 t2 = cadd(a[2], a[6]);
    float2 t3 = csub(a[2], a[6]);
    float2 E0 = cadd(t0, t2);
    float2 E2 = csub(t0, t2);
    float2 mt3 = cscale(S, mi(t3));
    float2 E1 = cadd(t1, mt3);
    float2 E3 = csub(t1, mt3);
    float2 u0 = cadd(a[1], a[5]);
    float2 u1 = csub(a[1], a[5]);
    float2 u2 = cadd(a[3], a[7]);
    float2 u3 = csub(a[3], a[7]);
    float2 O0 = cadd(u0, u2);
    float2 O2 = csub(u0, u2);
    float2 mu3 = cscale(S, mi(u3));
    float2 O1 = cadd(u1, mu3);
    float2 O3 = csub(u1, mu3);
    float2 w1 = cscale(c,  cadd(O1, cscale(S, mi(O1))));
    float2 w2 = cscale(S,  mi(O2));
    float2 w3 = cscale(-c, csub(O3, cscale(S, mi(O3))));
    b[0] = cadd(E0, O0);  b[4] = csub(E0, O0);
    b[1] = cadd(E1, w1);  b[5] = csub(E1, w1);
    b[2] = cadd(E2, w2);  b[6] = csub(E2, w2);
    b[3] = cadd(E3, w3);  b[7] = csub(E3, w3);
}

__device__ __forceinline__ void bfly6(float S, const float2 a[6], float2 b[6])
{
    const float s3 = 0.86602540378443864676f;
    float2 t1 = cadd(a[2], a[4]);
    float2 E0 = cadd(a[0], t1);
    float2 t2 = csub(a[0], cscale(0.5f, t1));
    float2 t3 = cscale(s3, csub(a[2], a[4]));
    float2 mt3 = cscale(S, mi(t3));
    float2 E1 = cadd(t2, mt3);
    float2 E2 = csub(t2, mt3);
    float2 v1 = cadd(a[3], a[5]);
    float2 O0 = cadd(a[1], v1);
    float2 v2 = csub(a[1], cscale(0.5f, v1));
    float2 v3 = cscale(s3, csub(a[3], a[5]));
    float2 mv3 = cscale(S, mi(v3));
    float2 O1 = cadd(v2, mv3);
    float2 O2 = csub(v2, mv3);
    float2 w1 = cadd(cscale( 0.5f, O1), cscale(S*s3, mi(O1)));
    float2 w2 = cadd(cscale(-0.5f, O2), cscale(S*s3, mi(O2)));
    b[0] = cadd(E0, O0);  b[3] = csub(E0, O0);
    b[1] = cadd(E1, w1);  b[4] = csub(E1, w1);
    b[2] = cadd(E2, w2);  b[5] = csub(E2, w2);
}

// every kernel builds forward twiddles locally (measured neutral vs table load)
__device__ __forceinline__ void build_tw_local(float2* tw)
{
    const int k = threadIdx.x;
    if (k < NFFT) {
        float sv, cv;
        sincosf((float)k * (float)(TWO_PI/384.0), &sv, &cv);
        tw[k] = make_float2(cv, -sv);
    }
}

// ---------------- FFT stage pieces ----------------
template<int SGN>
__device__ __forceinline__ void fft_stage1_smem(float2* A, float2* B, const float2* __restrict__ tw)
{
    constexpr float S = (float)SGN;
    const int t = threadIdx.x & (TT-1);
    const int p = threadIdx.x >> 4;
    float2 a[8], b[8];
#pragma unroll
    for (int j = 0; j < 8; ++j) a[j] = A[(p + 48*j)*ES + t];
    bfly8(S, a, b);
#pragma unroll
    for (int j = 1; j < 8; ++j) b[j] = cmul_t<SGN>(b[j], tw[p*j]);
#pragma unroll
    for (int j = 0; j < 8; ++j) B[(8*p + j)*ES + t] = b[j];
}

template<int SGN>
__device__ __forceinline__ void fft_stage2(float2* A, float2* B, const float2* __restrict__ tw)
{
    constexpr float S = (float)SGN;
    const int t = threadIdx.x & (TT-1);
    const int u = threadIdx.x >> 4;
    const int q = u & 7;
    const int p = u >> 3;
    const int base = q + 8*p;
    float2 a[8], b[8];
#pragma unroll
    for (int j = 0; j < 8; ++j) a[j] = B[(base + 48*j)*ES + t];
    bfly8(S, a, b);
#pragma unroll
    for (int j = 1; j < 8; ++j) b[j] = cmul_t<SGN>(b[j], tw[8*p*j]);
#pragma unroll
    for (int j = 0; j < 8; ++j) A[(q + 64*p + 8*j)*ES + t] = b[j];
}

template<int SGN>
__device__ __forceinline__ void fft384_stages12(float2* A, float2* B, const float2* __restrict__ tw)
{
    fft_stage1_smem<SGN>(A, B, tw);
    __syncthreads();
    fft_stage2<SGN>(A, B, tw);
    __syncthreads();
}

// generic stage-3 (t-major) item, used only by k_row_fwd
template<int SGN>
__device__ __forceinline__ void stage3_item(int i, const float2* A, float2* B)
{
    constexpr float S = (float)SGN;
    const int t = i & (TT-1);
    const int q = i >> 4;
    float2 a[6], b[6];
#pragma unroll
    for (int j = 0; j < 6; ++j) a[j] = A[(q + 64*j)*ES + t];
    bfly6(S, a, b);
#pragma unroll
    for (int j = 0; j < 6; ++j) B[(q + 64*j)*ES + t] = b[j];
}

template<int SGN>
__device__ __forceinline__ void fft384_tile(float2* A, float2* B, const float2* __restrict__ tw)
{
    fft384_stages12<SGN>(A, B, tw);
    stage3_item<SGN>(threadIdx.x, A, B);
    if (threadIdx.x < TT*64 - BLOCK)
        stage3_item<SGN>(threadIdx.x + BLOCK, A, B);
    __syncthreads();
}

// q-major stage-3: q = i & 63, t = i >> 6; smem reads conflict-free, epilogue coalesced
#define STAGE3_QMAJOR(SGNF, EPILOGUE)                                         \
    for (int rep = 0; rep < 2; ++rep) {                                       \
        const int i = threadIdx.x + rep*BLOCK;                                \
        if (i < TT*64) {                                                      \
            const int q = i & 63;                                             \
            const int t = i >> 6;                                             \
            float2 a[6], b[6];                                                \
            _Pragma("unroll")                                                 \
            for (int j = 0; j < 6; ++j) a[j] = A[(q + 64*j)*ES + t];          \
            bfly6(SGNF, a, b);                                                \
            EPILOGUE                                                          \
        }                                                                     \
    }

// ---------------- prep body: per-channel runT + ampsum-zero + rsum (4 elems/thread) ----------
__device__ __forceinline__ void prep_body(int ch, int pbid, const float* __restrict__ running)
{
    const int base = pbid*(BLOCK*4) + threadIdx.x;
    float s = 0.f;
#pragma unroll
    for (int m = 0; m < 4; ++m) {
        const int rem = base + m*BLOCK;
        if (rem < SPI) {
            const int w = rem / NFFT;
            const int h = rem - w*NFFT;
            const int hm = (NFFT - h) % NFFT;
            const int wm = (NFFT - w) % NFFT;
            const float a = running[ch*HW + h*NFFT + w];
            const float b = running[ch*HW + hm*NFFT + wm];
            const int idx = ch*SPI + rem;
            g_runT[idx]   = 0.5f*(a + b);
            g_ampsum[idx] = 0.f;                   // zeroed here; col_fwd(ch) follows on-stream
            // full-plane sum: direct terms cover w in [0,192]; mirrors cover [193,383].
            s += a + ((w >= 1 && w <= 191) ? b : 0.f);
        }
    }
#pragma unroll
    for (int o = 16; o > 0; o >>= 1) s += __shfl_down_sync(0xffffffffu, s, o);
    __shared__ float ws[BLOCK/32];
    if ((threadIdx.x & 31) == 0) ws[threadIdx.x >> 5] = s;
    __syncthreads();
    if (threadIdx.x < 32) {
        s = (threadIdx.x < BLOCK/32) ? ws[threadIdx.x] : 0.f;
#pragma unroll
        for (int o = 16; o > 0; o >>= 1) s += __shfl_down_sync(0xffffffffu, s, o);
        if (threadIdx.x == 0) atomicAdd(g_rsum, s);
    }
}

// ---------------- K1: per-channel packed row FFT + prep side blocks ----------------
__global__ void __launch_bounds__(BLOCK, 2) k_row_fwd(const float* __restrict__ x,
                                                      const float* __restrict__ running,
                                                      int ch)
{
    if (blockIdx.x >= ROWCH) { prep_body(ch, (int)blockIdx.x - ROWCH, running); return; }

    extern __shared__ float2 sm[];
    float2* A = sm;  float2* B = sm + BUF;  float2* tw = sm + 2*BUF;
    build_tw_local(tw);

    const int img = (blockIdx.x / ROWTILES)*NCH + ch;
    const int h0  = (blockIdx.x % ROWTILES) * 32;
    const float* xp = x + (size_t)img*HW + (size_t)h0*NFFT;

    const int r0 = threadIdx.x / NFFT;              // 0 or 1
    const int w  = threadIdx.x - r0*NFFT;           // 0..383
    const float* xb = xp + (size_t)(2*r0)*NFFT + w;
#pragma unroll
    for (int k = 0; k < 8; ++k) {                   // r = r0 + 2k
        A[w*ES + (r0 + 2*k)] =
            make_float2(xb[(size_t)(4*k)*NFFT], xb[(size_t)(4*k)*NFFT + NFFT]);
    }
    __syncthreads();
    fft384_tile<1>(A, B, tw);                       // packing needs mirrors: keep generic stage 3

    __half2* spH = g_specH + (size_t)img*SPI;
    for (int i = threadIdx.x; i < TT*W193; i += BLOCK) {
        const int t = i & (TT-1);
        const int ww = i >> 4;
        const int wm = ww ? NFFT - ww : 0;
        const float2 Z  = B[ww*ES + t];
        const float2 Zm = B[wm*ES + t];
        uint2 o2;
        o2.x = f2h(make_float2(0.5f*(Z.x + Zm.x), 0.5f*(Z.y - Zm.y)));   // F_even
        o2.y = f2h(make_float2(0.5f*(Z.y + Zm.y), 0.5f*(Zm.x - Z.x)));   // F_odd
        *reinterpret_cast<uint2*>(spH + (size_t)ww*NFFT + h0 + 2*t) = o2;
    }
}

// ---------------- K2: per-channel column FFT fwd + amplitude accumulate ----------------
__global__ void __launch_bounds__(BLOCK, 2) k_col_fwd(int ch)
{
    extern __shared__ float2 sm[];
    float2* A = sm;  float2* B = sm + BUF;  float2* tw = sm + 2*BUF;
    build_tw_local(tw);

    const int t0 = threadIdx.x / NFFT;              // 0 or 1
    const int h  = threadIdx.x - t0*NFFT;           // 0..383

    if (blockIdx.x < IPC*COLFULL) {
        const int img = (blockIdx.x / COLFULL)*NCH + ch;
        const int w0  = (blockIdx.x % COLFULL) * TT;
        const __half2* spHi = g_specH + (size_t)img*SPI + (size_t)w0*NFFT;
        float2* sp = g_spec + (size_t)img*SPI + (size_t)w0*NFFT;
#pragma unroll
        for (int k = 0; k < 8; ++k) {
            const int t = t0 + 2*k;
            A[h*ES + t] = __half22float2(spHi[(size_t)t*NFFT + h]);
        }
        __syncthreads();
        fft384_stages12<1>(A, B, tw);

        float* ab = g_ampsum + (size_t)ch*SPI + (size_t)w0*NFFT;
        STAGE3_QMAJOR(1.f,
#pragma unroll
            for (int j = 0; j < 6; ++j) {
                const size_t o = (size_t)t*NFFT + (q + 64*j);
                sp[o] = b[j];
                const float m2 = b[j].x*b[j].x + b[j].y*b[j].y;
                const float amp = (m2 > 0.f) ? m2*rsqrtf(m2) : 0.f;
                atomicAdd(&ab[o], amp);
            }
        )
    } else {
        const int g = blockIdx.x - IPC*COLFULL;     // 0..1 (image group, w=192)
#pragma unroll
        for (int k = 0; k < 8; ++k) {
            const int t = t0 + 2*k;
            const int img = (g*TT + t)*NCH + ch;
            A[h*ES + t] = __half22float2(g_specH[(size_t)img*SPI + (size_t)192*NFFT + h]);
        }
        __syncthreads();
        fft384_stages12<1>(A, B, tw);

        STAGE3_QMAJOR(1.f,
            const int img = (g*TT + t)*NCH + ch;
            float2* sp = g_spec + (size_t)img*SPI + (size_t)192*NFFT;
            float* ab = g_ampsum + (size_t)ch*SPI + (size_t)192*NFFT;
#pragma unroll
            for (int j = 0; j < 6; ++j) {
                const int hh = q + 64*j;
                sp[hh] = b[j];
                const float m2 = b[j].x*b[j].x + b[j].y*b[j].y;
                const float amp = (m2 > 0.f) ? m2*rsqrtf(m2) : 0.f;
                atomicAdd(&ab[hh], amp);
            }
        )
    }
}

// ---------------- K3: per-channel amplitude swap + column IFFT ----------------
__global__ void __launch_bounds__(BLOCK, 2) k_col_inv(int ch)
{
    extern __shared__ float2 sm[];
    float2* A = sm;  float2* B = sm + BUF;  float2* tw = sm + 2*BUF;
    build_tw_local(tw);

    const float rs = g_rsum[0];
    const float inv = 1.0f/147456.0f;               // full ifft2 normalization, folded here
    const int t0 = threadIdx.x / NFFT;
    const int h  = threadIdx.x - t0*NFFT;

#define COLINV_LOAD(SPOFF, ABOFF, T)                                          \
    {                                                                         \
        const float2 v = g_spec[SPOFF];                                       \
        const float mean = g_ampsum[ABOFF] * (1.0f/32.0f);                    \
        float na = mean;                                                      \
        if (rs != 0.0f) na = 0.9f*g_runT[ABOFF] + 0.1f*mean;                  \
        na *= inv;                                                            \
        const float m2 = v.x*v.x + v.y*v.y;                                   \
        float2 o;                                                             \
        if (m2 > 0.0f) { const float sc = na * rsqrtf(m2); o = make_float2(v.x*sc, v.y*sc); } \
        else           { o = make_float2(na, 0.0f); }                         \
        A[h*ES + (T)] = o;                                                    \
    }

    if (blockIdx.x < IPC*COLFULL) {
        const int img = (blockIdx.x / COLFULL)*NCH + ch;
        const int w0  = (blockIdx.x % COLFULL) * TT;
        const size_t spb = (size_t)img*SPI + (size_t)w0*NFFT;
        const size_t abb = (size_t)ch*SPI + (size_t)w0*NFFT;
#pragma unroll 4
        for (int k = 0; k < 8; ++k) {
            const int t = t0 + 2*k;
            const size_t o = (size_t)t*NFFT + h;
            COLINV_LOAD(spb + o, abb + o, t)
        }
        __syncthreads();
        fft384_stages12<-1>(A, B, tw);

        __half2* spH = g_specH + spb;
        STAGE3_QMAJOR(-1.f,
#pragma unroll
            for (int j = 0; j < 6; ++j)
                spH[(size_t)t*NFFT + (q + 64*j)] = __float22half2_rn(b[j]);
        )
    } else {
        const int g = blockIdx.x - IPC*COLFULL;     // 0..1
#pragma unroll 4
        for (int k = 0; k < 8; ++k) {
            const int t = t0 + 2*k;
            const int img = (g*TT + t)*NCH + ch;
            const size_t spo = (size_t)img*SPI + (size_t)192*NFFT + h;
            const size_t abo = (size_t)ch*SPI + (size_t)192*NFFT + h;
            COLINV_LOAD(spo, abo, t)
        }
        __syncthreads();
        fft384_stages12<-1>(A, B, tw);

        STAGE3_QMAJOR(-1.f,
            const int img = (g*TT + t)*NCH + ch;
            __half2* spH = g_specH + (size_t)img*SPI + (size_t)192*NFFT;
#pragma unroll
            for (int j = 0; j < 6; ++j)
                spH[q + 64*j] = __float22half2_rn(b[j]);
        )
    }
#undef COLINV_LOAD
}

// ---------------- K4: per-channel packed row IFFT (C2R, register-mirrored stage 1) ----------
__global__ void __launch_bounds__(BLOCK, 2) k_row_inv(float* __restrict__ out, int ch)
{
    extern __shared__ float2 sm[];
    float2* A = sm;  float2* B = sm + BUF;  float2* tw = sm + 2*BUF;
    build_tw_local(tw);

    const int img = (blockIdx.x / ROWTILES)*NCH + ch;
    const int h0  = (blockIdx.x % ROWTILES) * 32;
    const __half2* spH = g_specH + (size_t)img*SPI;

    __syncthreads();                                // tw visible before stage 1 uses it
    {   // ---- stage 1: gmem(fp16) -> B, mirror on the fly ----
        const int t = threadIdx.x & (TT-1);
        const int p = threadIdx.x >> 4;             // 0..47
        float2 a[8], b[8];
#pragma unroll
        for (int j = 0; j < 8; ++j) {
            const int e  = p + 48*j;                // 0..383
            const int em = (e <= 192) ? e : NFFT - e;
            uint2 zz = *reinterpret_cast<const uint2*>(spH + (size_t)em*NFFT + h0 + 2*t);
            const float2 ze = h2f(zz.x), zo = h2f(zz.y);
            // W[e] = Z_e + i*Z_o ; W[e>192] = conj(Z_e[384-e]) + i*conj(Z_o[384-e])
            a[j] = (e <= 192) ? make_float2(ze.x - zo.y, ze.y + zo.x)
                              : make_float2(ze.x + zo.y, zo.x - ze.y);
        }
        bfly8(-1.f, a, b);
#pragma unroll
        for (int j = 1; j < 8; ++j) b[j] = cmul_t<-1>(b[j], tw[p*j]);
#pragma unroll
        for (int j = 0; j < 8; ++j) B[(8*p + j)*ES + t] = b[j];
    }
    __syncthreads();
    fft_stage2<-1>(A, B, tw);
    __syncthreads();

    float* op = out + (size_t)img*HW + (size_t)h0*NFFT;   // norm already folded in col_inv
    STAGE3_QMAJOR(-1.f,
        float* o0 = op + (size_t)(2*t)*NFFT;
        float* o1 = o0 + NFFT;
#pragma unroll
        for (int j = 0; j < 6; ++j) {
            const int w = q + 64*j;
            o0[w] = b[j].x;       // even output row 2t
            o1[w] = b[j].y;       // odd output row 2t+1
        }
    )
}

// ---------------- launch: 3 channel chains on 3 streams (R14/R16 structure) ----------------
extern "C" void kernel_launch(void* const* d_in, const int* in_sizes, int n_in,
                              void* d_out, int out_size)
{
    const float* x       = (const float*)d_in[0];
    const float* running = (const float*)d_in[1];
    float* out = (float*)d_out;

    static cudaStream_t st[NCH];
    static cudaEvent_t evFork, evRow[NCH], evJoin[NCH];
    static bool inited = false;
    if (!inited) {
        for (int c = 0; c < NCH; ++c)
            cudaStreamCreateWithFlags(&st[c], cudaStreamNonBlocking);
        cudaEventCreateWithFlags(&evFork, cudaEventDisableTiming);
        for (int c = 0; c < NCH; ++c) {
            cudaEventCreateWithFlags(&evRow[c],  cudaEventDisableTiming);
            cudaEventCreateWithFlags(&evJoin[c], cudaEventDisableTiming);
        }
        inited = true;
    }

    void* p_rs = nullptr;  cudaGetSymbolAddress(&p_rs, g_rsum);

    cudaFuncSetAttribute(k_row_fwd, cudaFuncAttributeMaxDynamicSharedMemorySize, SMEM_BYTES);
    cudaFuncSetAttribute(k_col_fwd, cudaFuncAttributeMaxDynamicSharedMemorySize, SMEM_BYTES);
    cudaFuncSetAttribute(k_col_inv, cudaFuncAttributeMaxDynamicSharedMemorySize, SMEM_BYTES);
    cudaFuncSetAttribute(k_row_inv, cudaFuncAttributeMaxDynamicSharedMemorySize, SMEM_BYTES);

    // zero rsum on the captured (legacy) stream, then fork (ampsum zeroed inside prep)
    cudaMemsetAsync(p_rs, 0, sizeof(float));
    cudaEventRecord(evFork, 0);

    for (int c = 0; c < NCH; ++c) {
        cudaStreamWaitEvent(st[c], evFork, 0);
        k_row_fwd<<<ROWCH + PREPC, BLOCK, SMEM_BYTES, st[c]>>>(x, running, c);
        cudaEventRecord(evRow[c], st[c]);
    }
    for (int c = 0; c < NCH; ++c) {
        k_col_fwd<<<COLCH, BLOCK, SMEM_BYTES, st[c]>>>(c);
        // col_inv needs ALL prep (rsum/runT): wait on the other channels' row kernels
        cudaStreamWaitEvent(st[c], evRow[(c + 1) % NCH], 0);
        cudaStreamWaitEvent(st[c], evRow[(c + 2) % NCH], 0);
        k_col_inv<<<COLCH, BLOCK, SMEM_BYTES, st[c]>>>(c);
        k_row_inv<<<ROWCH, BLOCK, SMEM_BYTES, st[c]>>>(out, c);
        cudaEventRecord(evJoin[c], st[c]);
    }
    for (int c = 0; c < NCH; ++c)
        cudaStreamWaitEvent(0, evJoin[c], 0);      // join back to the captured stream
}